// round 12
// baseline (speedup 1.0000x reference)
#include <cuda_runtime.h>
#include <cuda_bf16.h>
#include <cstdint>

#ifndef HELM_PI
#define HELM_PI 3.14159265358979323846f
#endif

// out[i] = (a^2 - 2*pi^2) * sin(pi*x0) * sin(pi*x1)
//
// 256-bit load variant: thread t of block b loads 32B chunks (8 floats =
// 4 rows) at chunk indices 512b+t and 512b+256+t via ld.global.v8.b32.
// Fully coalesced (one 1024B burst per warp-load). Each chunk yields one
// float4 of outputs, stored evict-first at the matching index.

struct f8 { float v[8]; };

__device__ __forceinline__ f8 ld256(const float* p) {
    uint32_t r0, r1, r2, r3, r4, r5, r6, r7;
    asm volatile("ld.global.v8.b32 {%0,%1,%2,%3,%4,%5,%6,%7}, [%8];"
                 : "=r"(r0), "=r"(r1), "=r"(r2), "=r"(r3),
                   "=r"(r4), "=r"(r5), "=r"(r6), "=r"(r7)
                 : "l"(p));
    f8 out;
    out.v[0] = __uint_as_float(r0); out.v[1] = __uint_as_float(r1);
    out.v[2] = __uint_as_float(r2); out.v[3] = __uint_as_float(r3);
    out.v[4] = __uint_as_float(r4); out.v[5] = __uint_as_float(r5);
    out.v[6] = __uint_as_float(r6); out.v[7] = __uint_as_float(r7);
    return out;
}

__global__ void __launch_bounds__(256) helm_kernel(
    const float* __restrict__ in,     // [N,2] interleaved
    const float* __restrict__ a,
    float4*      __restrict__ out4,   // N/4 float4s
    int nc)                            // number of 32B chunks = N/4
{
    size_t c0 = (size_t)blockIdx.x * 512 + threadIdx.x;
    size_t c1 = c0 + 256;

    // Two independent, fully-coalesced 256-bit loads (front-batched)
    f8 u0 = ld256(in + c0 * 8);
    f8 u1 = ld256(in + c1 * 8);

    const float pi = HELM_PI;
    float av = __ldg(a);
    float coef = fmaf(av, av, -2.0f * pi * pi);

    float4 o0, o1;
    o0.x = coef * __sinf(pi * u0.v[0]) * __sinf(pi * u0.v[1]);
    o0.y = coef * __sinf(pi * u0.v[2]) * __sinf(pi * u0.v[3]);
    o0.z = coef * __sinf(pi * u0.v[4]) * __sinf(pi * u0.v[5]);
    o0.w = coef * __sinf(pi * u0.v[6]) * __sinf(pi * u0.v[7]);
    o1.x = coef * __sinf(pi * u1.v[0]) * __sinf(pi * u1.v[1]);
    o1.y = coef * __sinf(pi * u1.v[2]) * __sinf(pi * u1.v[3]);
    o1.z = coef * __sinf(pi * u1.v[4]) * __sinf(pi * u1.v[5]);
    o1.w = coef * __sinf(pi * u1.v[6]) * __sinf(pi * u1.v[7]);

    if (c0 < (size_t)nc) __stcs(out4 + c0, o0);
    if (c1 < (size_t)nc) __stcs(out4 + c1, o1);
}

extern "C" void kernel_launch(void* const* d_in, const int* in_sizes, int n_in,
                              void* d_out, int out_size)
{
    const float* in = (const float*)d_in[0];   // [N,2] float32
    const float* a  = (const float*)d_in[1];   // [1] float32

    int nc = in_sizes[0] / 8;   // number of 32B chunks = N/4 (N = 2^24)

    const int threads = 256;
    int blocks = (nc + 2 * threads - 1) / (2 * threads);  // 512 chunks per block

    helm_kernel<<<blocks, threads>>>(
        in, a, (float4*)d_out, nc);
}